// round 16
// baseline (speedup 1.0000x reference)
#include <cuda_runtime.h>
#include <stdint.h>

#define TOKENS 16384
#define DIM    4096
#define NE     64
#define BM     64
#define NTHR   256
#define TAU    8e-3f
#define MAXF   32

// W in fp16 B-fragment order with k-permutation (R14 layout):
// [kstep j 0..255][nblk 0..7][lane 0..31] -> uint2{b0,b1}
__device__ __align__(16) uint2 g_wfrag[256 * 8 * 32];

// ---- smem: x ring 4 x 8KB (fp16, swizzled) + B ring 4 x 8KB ----
#define XSLOT  8192
#define BS_OFF 32768
#define BSTAGE 8192
#define SMEM_TOTAL 65536
// ---- epilogue aliases (post-mainloop only) ----
#define SLOG_OFF   32768             // 64 x 65 fp32
#define S1_OFF     49408
#define S2_OFF     49664
#define I1_OFF     49920
#define I2_OFF     50176
#define FENT_OFF   50432
#define NFLAG_OFF  50688
#define FTOK_OFF   50692
#define FCAND_OFF  50820
#define FVAL_OFF   51332

__device__ __forceinline__ uint32_t smem_u32(const void* p) {
    uint32_t a;
    asm("{ .reg .u64 t; cvta.to.shared.u64 t, %1; cvt.u32.u64 %0, t; }"
        : "=r"(a) : "l"(p));
    return a;
}

__device__ __forceinline__ uint32_t pack_f16x2(float f0, float f1) {
    uint32_t r;
    asm("cvt.rn.f16x2.f32 %0, %1, %2;" : "=r"(r) : "f"(f1), "f"(f0));  // f0 -> low
    return r;
}

__device__ __forceinline__ void mma16816(float c[4], const uint32_t a[4],
                                         uint32_t b0, uint32_t b1) {
    asm volatile(
        "mma.sync.aligned.m16n8k16.row.col.f32.f16.f16.f32 "
        "{%0,%1,%2,%3}, {%4,%5,%6,%7}, {%8,%9}, {%0,%1,%2,%3};"
        : "+f"(c[0]), "+f"(c[1]), "+f"(c[2]), "+f"(c[3])
        : "r"(a[0]), "r"(a[1]), "r"(a[2]), "r"(a[3]), "r"(b0), "r"(b1));
}

// ---------------- prep: W fp32 -> fp16 fragments, permuted-k order ----------------
__global__ void prep_w(const float* __restrict__ W) {
    int idx = blockIdx.x * 256 + threadIdx.x;      // 0..65535
    int j    = idx >> 8;
    int lane = idx & 31;
    int nb   = (idx >> 5) & 7;
    int n = nb * 8 + (lane >> 2);
    int k = j * 16 + (lane & 3) * 4;
    float4 v = *reinterpret_cast<const float4*>(W + (size_t)n * DIM + k);
    g_wfrag[idx] = make_uint2(pack_f16x2(v.x, v.y), pack_f16x2(v.z, v.w));
}

// ---------------- main fused kernel: fp16 x-staging, 4-stage pipelines ----------------
__global__ __launch_bounds__(NTHR, 2)
void topk_gate_pipe6(const float* __restrict__ x, const float* __restrict__ Wf,
                     float* __restrict__ out_logits, float* __restrict__ out_scores,
                     float* __restrict__ out_loss)
{
    extern __shared__ char smem[];
    const uint32_t sb = smem_u32(smem);

    float* red   = reinterpret_cast<float*>(smem);
    float* slog  = reinterpret_cast<float*>(smem + SLOG_OFF);
    float* s_s1  = reinterpret_cast<float*>(smem + S1_OFF);
    float* s_s2  = reinterpret_cast<float*>(smem + S2_OFF);
    int*   s_i1  = reinterpret_cast<int*>(smem + I1_OFF);
    int*   s_i2  = reinterpret_cast<int*>(smem + I2_OFF);
    int*   s_fent= reinterpret_cast<int*>(smem + FENT_OFF);
    int*   s_nfl = reinterpret_cast<int*>(smem + NFLAG_OFF);
    int*   f_tok = reinterpret_cast<int*>(smem + FTOK_OFF);
    int*   f_cand= reinterpret_cast<int*>(smem + FCAND_OFF);
    float* f_val = reinterpret_cast<float*>(smem + FVAL_OFF);

    const int tid  = threadIdx.x;
    const int lane = tid & 31;
    const int wid  = tid >> 5;
    const int mh   = wid >> 2;          // m-half 0..1
    const int ks   = wid & 3;           // k-slice 0..3
    const size_t m_base = (size_t)blockIdx.x * BM;

    // ---- x producer mapping: thread -> row (tid>>2), phys 32B block cc=tid&3 ----
    // logical k-chunk in this block: jlog = cc ^ (row&3)  (swizzle)
    const int crow = tid >> 2;
    const int cc   = tid & 3;
    const int jlog = cc ^ (crow & 3);
    const float* xg   = x + m_base * DIM;
    const float* xrow = xg + (size_t)crow * DIM + jlog * 16;
    char* xsts = smem + crow * 128 + cc * 32;    // + slot*XSLOT

    // ---- B copy (cp.async, unchanged from R14) ----
#define COPY_B(S, ST)                                                          \
    do {                                                                       \
        const char* _gb = reinterpret_cast<const char*>(g_wfrag)               \
                          + (size_t)(S) * BSTAGE + tid * 32;                   \
        uint32_t _bd = sb + BS_OFF + (ST) * BSTAGE + tid * 32;                 \
        asm volatile("cp.async.cg.shared.global [%0], [%1], 16;"               \
                     :: "r"(_bd), "l"(_gb));                                   \
        asm volatile("cp.async.cg.shared.global [%0], [%1], 16;"               \
                     :: "r"(_bd + 16), "l"(_gb + 16));                         \
        asm volatile("cp.async.commit_group;");                                \
    } while (0)

    // ---- consumer loop-invariant offsets ----
    const int t   = lane & 3;
    const int rq  = lane >> 2;                      // 0..7
    const int aoff = (mh * 32 + rq) * 128 + (ks ^ (rq & 3)) * 32 + t * 8;
    const int boff = ks * 2048 + lane * 8;

    float acc[2][4][4], acc2[2][4][4];
    #pragma unroll
    for (int mg = 0; mg < 2; mg++)
        #pragma unroll
        for (int nt = 0; nt < 4; nt++)
            #pragma unroll
            for (int q = 0; q < 4; q++) { acc[mg][nt][q] = 0.f; acc2[mg][nt][q] = 0.f; }

    // LDG register buffer for x (one stage in flight)
    float4 vb0, vb1, vb2, vb3;

#define LDG_X(S)                                                               \
    do {                                                                       \
        const float* p = xrow + (size_t)(S) * 64;                              \
        vb0 = *reinterpret_cast<const float4*>(p);                             \
        vb1 = *reinterpret_cast<const float4*>(p + 4);                         \
        vb2 = *reinterpret_cast<const float4*>(p + 8);                         \
        vb3 = *reinterpret_cast<const float4*>(p + 12);                        \
    } while (0)

#define STS_X(SLOT)                                                            \
    do {                                                                       \
        uint4 u0, u1;                                                          \
        u0.x = pack_f16x2(vb0.x, vb0.y);                                       \
        u0.y = pack_f16x2(vb0.z, vb0.w);                                       \
        u0.z = pack_f16x2(vb1.x, vb1.y);                                       \
        u0.w = pack_f16x2(vb1.z, vb1.w);                                       \
        u1.x = pack_f16x2(vb2.x, vb2.y);                                       \
        u1.y = pack_f16x2(vb2.z, vb2.w);                                       \
        u1.z = pack_f16x2(vb3.x, vb3.y);                                       \
        u1.w = pack_f16x2(vb3.z, vb3.w);                                       \
        char* _d = xsts + (SLOT) * XSLOT;                                      \
        *reinterpret_cast<uint4*>(_d)      = u0;                               \
        *reinterpret_cast<uint4*>(_d + 16) = u1;                               \
    } while (0)

    // ---- prologue: x slots 0,1 staged; B stages 0,1,2 in flight ----
    LDG_X(0); STS_X(0);
    LDG_X(1); STS_X(1);
    COPY_B(0, 0);
    COPY_B(1, 1);
    COPY_B(2, 2);

    #pragma unroll 1
    for (int s = 0; s < 64; ++s) {
        asm volatile("cp.async.wait_group 2;" ::: "memory");
        __syncthreads();

        // x LDG for stage s+2 (registers; STS at end of this iteration)
        {
            const int sn = (s + 2 < 64) ? (s + 2) : 63;
            LDG_X(sn);
        }
        // B refill for stage s+3
        if (s + 3 < 64) COPY_B(s + 3, (s + 3) & 3);
        else asm volatile("cp.async.commit_group;");

        const char* xb = smem + (s & 3) * XSLOT;
        const char* bb = smem + BS_OFF + (s & 3) * BSTAGE + boff;

        // B fragments (conflict-free LDS.64)
        const uint2 q0 = *reinterpret_cast<const uint2*>(bb);
        const uint2 q1 = *reinterpret_cast<const uint2*>(bb + 256);
        const uint2 q2 = *reinterpret_cast<const uint2*>(bb + 512);
        const uint2 q3 = *reinterpret_cast<const uint2*>(bb + 768);
        const uint2 q4 = *reinterpret_cast<const uint2*>(bb + 1024);
        const uint2 q5 = *reinterpret_cast<const uint2*>(bb + 1280);
        const uint2 q6 = *reinterpret_cast<const uint2*>(bb + 1536);
        const uint2 q7 = *reinterpret_cast<const uint2*>(bb + 1792);

        // A fragments: fp16 direct, 4 conflict-free LDS.64 (rows r0,+8,+16,+24)
        const uint2 A0 = *reinterpret_cast<const uint2*>(xb + aoff);
        const uint2 A1 = *reinterpret_cast<const uint2*>(xb + aoff + 1024);
        const uint2 A2 = *reinterpret_cast<const uint2*>(xb + aoff + 2048);
        const uint2 A3 = *reinterpret_cast<const uint2*>(xb + aoff + 3072);

        uint32_t a0[4], a1[4];
        a0[0] = A0.x; a0[1] = A1.x; a0[2] = A0.y; a0[3] = A1.y;
        a1[0] = A2.x; a1[1] = A3.x; a1[2] = A2.y; a1[3] = A3.y;

        // 16 independent mmas
        mma16816(acc[0][0], a0, q0.x, q0.y);
        mma16816(acc[0][1], a0, q1.x, q1.y);
        mma16816(acc[0][2], a0, q2.x, q2.y);
        mma16816(acc[0][3], a0, q3.x, q3.y);
        mma16816(acc[1][0], a1, q0.x, q0.y);
        mma16816(acc[1][1], a1, q1.x, q1.y);
        mma16816(acc[1][2], a1, q2.x, q2.y);
        mma16816(acc[1][3], a1, q3.x, q3.y);
        mma16816(acc2[0][0], a0, q4.x, q4.y);
        mma16816(acc2[0][1], a0, q5.x, q5.y);
        mma16816(acc2[0][2], a0, q6.x, q6.y);
        mma16816(acc2[0][3], a0, q7.x, q7.y);
        mma16816(acc2[1][0], a1, q4.x, q4.y);
        mma16816(acc2[1][1], a1, q5.x, q5.y);
        mma16816(acc2[1][2], a1, q6.x, q6.y);
        mma16816(acc2[1][3], a1, q7.x, q7.y);

        // stage x(s+2) into slot (s+2)&3 (readers of this slot finished in iter s-2)
        STS_X((s + 2) & 3);
    }

    asm volatile("cp.async.wait_group 0;" ::: "memory");
    __syncthreads();    // all compute done before aliasing stage buffers
    if (tid == 0) *s_nfl = 0;

    // ---- k-slice tree reduction ----
    const int slot = mh * 2 + (ks >> 1);
    float* rp = red + slot * 2048;

    if (ks & 1) {
        #pragma unroll
        for (int mg = 0; mg < 2; mg++)
            #pragma unroll
            for (int nt = 0; nt < 4; nt++)
                #pragma unroll
                for (int q = 0; q < 4; q++) {
                    rp[(mg * 32 + nt * 4 + q) * 32 + lane] = acc[mg][nt][q];
                    rp[(mg * 32 + (nt + 4) * 4 + q) * 32 + lane] = acc2[mg][nt][q];
                }
    }
    __syncthreads();
    if (!(ks & 1)) {
        #pragma unroll
        for (int mg = 0; mg < 2; mg++)
            #pragma unroll
            for (int nt = 0; nt < 4; nt++)
                #pragma unroll
                for (int q = 0; q < 4; q++) {
                    acc[mg][nt][q]  += rp[(mg * 32 + nt * 4 + q) * 32 + lane];
                    acc2[mg][nt][q] += rp[(mg * 32 + (nt + 4) * 4 + q) * 32 + lane];
                }
    }
    __syncthreads();
    if (ks == 2) {
        float* rp2 = red + (mh * 2) * 2048;
        #pragma unroll
        for (int mg = 0; mg < 2; mg++)
            #pragma unroll
            for (int nt = 0; nt < 4; nt++)
                #pragma unroll
                for (int q = 0; q < 4; q++) {
                    rp2[(mg * 32 + nt * 4 + q) * 32 + lane] = acc[mg][nt][q];
                    rp2[(mg * 32 + (nt + 4) * 4 + q) * 32 + lane] = acc2[mg][nt][q];
                }
    }
    __syncthreads();
    if (ks == 0) {
        const float* rp2 = red + (mh * 2) * 2048;
        const int gr = lane >> 2;
        const int gc = (lane & 3) * 2;
        #pragma unroll
        for (int mg = 0; mg < 2; mg++) {
            const int rr0 = mh * 32 + mg * 16 + gr;
            #pragma unroll
            for (int nt = 0; nt < 8; nt++) {
                float* a = (nt < 4) ? acc[mg][nt] : acc2[mg][nt - 4];
                float c0 = a[0] + rp2[(mg * 32 + nt * 4 + 0) * 32 + lane];
                float c1 = a[1] + rp2[(mg * 32 + nt * 4 + 1) * 32 + lane];
                float c2 = a[2] + rp2[(mg * 32 + nt * 4 + 2) * 32 + lane];
                float c3 = a[3] + rp2[(mg * 32 + nt * 4 + 3) * 32 + lane];
                const int ccl = nt * 8 + gc;
                slog[rr0 * 65 + ccl]           = c0;
                slog[rr0 * 65 + ccl + 1]       = c1;
                slog[(rr0 + 8) * 65 + ccl]     = c2;
                slog[(rr0 + 8) * 65 + ccl + 1] = c3;
            }
        }
    }
    __syncthreads();

    // ---- per-token scan: top-4, logsumexp, flag near-ties ----
    if (tid < BM) {
        const float* r = slog + tid * 65;
        float m1 = -3.4e38f, m2 = -3.4e38f, m3 = -3.4e38f, m4 = -3.4e38f;
        int i1 = 0, i2 = 0, i3 = 0, i4 = 0;
        #pragma unroll
        for (int e = 0; e < NE; e++) {
            float v = r[e];
            if (v > m1)      { m4=m3;i4=i3; m3=m2;i3=i2; m2=m1;i2=i1; m1=v;i1=e; }
            else if (v > m2) { m4=m3;i4=i3; m3=m2;i3=i2; m2=v;i2=e; }
            else if (v > m3) { m4=m3;i4=i3; m3=v;i3=e; }
            else if (v > m4) { m4=v;i4=e; }
        }
        float sum = 0.f;
        #pragma unroll
        for (int e = 0; e < NE; e++) sum += expf(r[e] - m1);
        float lz = m1 + logf(sum);
        out_loss[m_base + tid] = lz * lz;

        float dd = expf(m2 - m1);
        float s1 = 1.f / (1.f + dd);
        s_s1[tid] = s1;
        s_s2[tid] = dd * s1;
        s_i1[tid] = i1;
        s_i2[tid] = i2;

        int ent = -1;
        if (m2 - m3 < TAU) {
            int fs = atomicAdd(s_nfl, 1);
            if (fs < MAXF) {
                ent = fs;
                f_tok[ent] = tid;
                f_cand[ent * 4 + 0] = i1;
                f_cand[ent * 4 + 1] = i2;
                f_cand[ent * 4 + 2] = i3;
                f_cand[ent * 4 + 3] = i4;
            }
        }
        s_fent[tid] = ent;
    }
    __syncthreads();

    // ---- exact fp32 refinement: one warp per (flagged token, candidate) ----
    {
        int nf = *s_nfl; if (nf > MAXF) nf = MAXF;
        for (int task = wid; task < nf * 4; task += 8) {
            const int fi = task >> 2, c = task & 3;
            const int tok = f_tok[fi];
            const int expert = f_cand[fi * 4 + c];
            const float* xr = x + (m_base + tok) * DIM;
            const float* wr = Wf + (size_t)expert * DIM;
            float a4[4] = {0.f, 0.f, 0.f, 0.f};
            for (int k = lane * 4; k < DIM; k += 128) {
                float4 xv = *reinterpret_cast<const float4*>(xr + k);
                float4 wv = *reinterpret_cast<const float4*>(wr + k);
                a4[0] = fmaf(xv.x, wv.x, a4[0]);
                a4[1] = fmaf(xv.y, wv.y, a4[1]);
                a4[2] = fmaf(xv.z, wv.z, a4[2]);
                a4[3] = fmaf(xv.w, wv.w, a4[3]);
            }
            float sum = (a4[0] + a4[1]) + (a4[2] + a4[3]);
            #pragma unroll
            for (int off = 16; off; off >>= 1)
                sum += __shfl_xor_sync(0xffffffffu, sum, off);
            if (lane == 0) f_val[fi * 4 + c] = sum;
        }
    }
    __syncthreads();

    // ---- flagged tokens: re-pick exact top-2 (stable ties by lower index) ----
    if (tid < BM && s_fent[tid] >= 0) {
        const int ent = s_fent[tid];
        float v1 = -3.4e38f, v2 = -3.4e38f;
        int j1 = NE, j2 = NE;
        #pragma unroll
        for (int c = 0; c < 4; c++) {
            float v = f_val[ent * 4 + c];
            int   j = f_cand[ent * 4 + c];
            bool b1 = (v > v1) || (v == v1 && j < j1);
            bool b2 = (v > v2) || (v == v2 && j < j2);
            if (b1)      { v2 = v1; j2 = j1; v1 = v; j1 = j; }
            else if (b2) { v2 = v; j2 = j; }
        }
        float dd = expf(v2 - v1);
        float s1 = 1.f / (1.f + dd);
        s_s1[tid] = s1;
        s_s2[tid] = dd * s1;
        s_i1[tid] = j1;
        s_i2[tid] = j2;
    }
    __syncthreads();

    // ---- stores ----
    float* lg = out_logits + m_base * NE;
    float* sc = out_scores + m_base * NE;
    #pragma unroll
    for (int pass = 0; pass < (BM * NE) / NTHR; pass++) {
        int idx = pass * NTHR + tid;
        int tt = idx >> 6;
        int e = idx & 63;
        lg[idx] = slog[tt * 65 + e];
        float sv = (e == s_i1[tt]) ? s_s1[tt] : ((e == s_i2[tt]) ? s_s2[tt] : 0.f);
        sc[idx] = sv;
    }
#undef COPY_B
#undef LDG_X
#undef STS_X
}

extern "C" void kernel_launch(void* const* d_in, const int* in_sizes, int n_in,
                              void* d_out, int out_size)
{
    const float* x = (const float*)d_in[0];
    const float* W = (const float*)d_in[1];
    float* out    = (float*)d_out;
    float* logits = out;
    float* scores = out + (size_t)TOKENS * NE;
    float* loss   = out + (size_t)2 * TOKENS * NE;

    prep_w<<<256, 256>>>(W);

    cudaFuncSetAttribute(topk_gate_pipe6,
                         cudaFuncAttributeMaxDynamicSharedMemorySize, SMEM_TOTAL);
    topk_gate_pipe6<<<TOKENS / BM, NTHR, SMEM_TOTAL>>>(x, W, logits, scores, loss);
}

// round 17
// speedup vs baseline: 1.4588x; 1.4588x over previous
#include <cuda_runtime.h>
#include <stdint.h>

#define TOKENS 16384
#define DIM    4096
#define NE     64
#define BM     64
#define NTHR   256
#define TAU    8e-3f
#define MAXF   32

// W in fp16 B-fragment order with k-permutation (R14 layout):
// [kstep j 0..255][nblk 0..7][lane 0..31] -> uint2{b0,b1}
__device__ __align__(16) uint2 g_wfrag[256 * 8 * 32];

// ---- smem: 3-stage ring of 8 warp-private 4KB slabs ----
// slab: [0,2048)  x slice: 32 rows x 64B fp32, swizzled 16B chunks
//       [2048,4096) B slice: 8 nblk x 256B (this warp's kstep)
#define WSLAB 4096
#define STG   32768
#define SMEM_TOTAL (3 * STG)         // 98304
// ---- epilogue aliases (post-mainloop only) ----
#define SLOG_OFF   32768             // 64 x 65 fp32
#define S1_OFF     49408
#define S2_OFF     49664
#define I1_OFF     49920
#define I2_OFF     50176
#define FENT_OFF   50432
#define NFLAG_OFF  50688
#define FTOK_OFF   50692
#define FCAND_OFF  50820
#define FVAL_OFF   51332

__device__ __forceinline__ uint32_t smem_u32(const void* p) {
    uint32_t a;
    asm("{ .reg .u64 t; cvta.to.shared.u64 t, %1; cvt.u32.u64 %0, t; }"
        : "=r"(a) : "l"(p));
    return a;
}

__device__ __forceinline__ uint32_t pack_f16x2(float f0, float f1) {
    uint32_t r;
    asm("cvt.rn.f16x2.f32 %0, %1, %2;" : "=r"(r) : "f"(f1), "f"(f0));  // f0 -> low
    return r;
}

__device__ __forceinline__ void mma16816(float c[4], const uint32_t a[4],
                                         uint32_t b0, uint32_t b1) {
    asm volatile(
        "mma.sync.aligned.m16n8k16.row.col.f32.f16.f16.f32 "
        "{%0,%1,%2,%3}, {%4,%5,%6,%7}, {%8,%9}, {%0,%1,%2,%3};"
        : "+f"(c[0]), "+f"(c[1]), "+f"(c[2]), "+f"(c[3])
        : "r"(a[0]), "r"(a[1]), "r"(a[2]), "r"(a[3]), "r"(b0), "r"(b1));
}

// ---------------- prep: W fp32 -> fp16 fragments, permuted-k order ----------------
__global__ void prep_w(const float* __restrict__ W) {
    int idx = blockIdx.x * 256 + threadIdx.x;      // 0..65535
    int j    = idx >> 8;
    int lane = idx & 31;
    int nb   = (idx >> 5) & 7;
    int n = nb * 8 + (lane >> 2);
    int k = j * 16 + (lane & 3) * 4;
    float4 v = *reinterpret_cast<const float4*>(W + (size_t)n * DIM + k);
    g_wfrag[idx] = make_uint2(pack_f16x2(v.x, v.y), pack_f16x2(v.z, v.w));
}

// ---------------- main fused kernel: warp-private cp.async pipelines ----------------
__global__ __launch_bounds__(NTHR, 2)
void topk_gate_wp(const float* __restrict__ x, const float* __restrict__ Wf,
                  float* __restrict__ out_logits, float* __restrict__ out_scores,
                  float* __restrict__ out_loss)
{
    extern __shared__ char smem[];
    const uint32_t sb = smem_u32(smem);

    float* red   = reinterpret_cast<float*>(smem);
    float* slog  = reinterpret_cast<float*>(smem + SLOG_OFF);
    float* s_s1  = reinterpret_cast<float*>(smem + S1_OFF);
    float* s_s2  = reinterpret_cast<float*>(smem + S2_OFF);
    int*   s_i1  = reinterpret_cast<int*>(smem + I1_OFF);
    int*   s_i2  = reinterpret_cast<int*>(smem + I2_OFF);
    int*   s_fent= reinterpret_cast<int*>(smem + FENT_OFF);
    int*   s_nfl = reinterpret_cast<int*>(smem + NFLAG_OFF);
    int*   f_tok = reinterpret_cast<int*>(smem + FTOK_OFF);
    int*   f_cand= reinterpret_cast<int*>(smem + FCAND_OFF);
    float* f_val = reinterpret_cast<float*>(smem + FVAL_OFF);

    const int tid  = threadIdx.x;
    const int lane = tid & 31;
    const int wid  = tid >> 5;
    const int mh   = wid >> 2;          // m-half 0..1
    const int ks   = wid & 3;           // k-slice 0..3
    const size_t m_base = (size_t)blockIdx.x * BM;

    // ---- producer mapping (per warp): lane -> (row lrow+8p, chunk lt) ----
    const int lrow = lane >> 2;                       // 0..7
    const int lt   = lane & 3;                        // 16B chunk (k-perm group)
    const uint32_t xdst = (uint32_t)(lrow * 64 + (((lt ^ lrow) & 3) << 4));
    const float* xwarp = x + (m_base + mh * 32 + lrow) * DIM + ks * 16 + lt * 4;
    const uint32_t slabbase = sb + (uint32_t)wid * WSLAB;

#define COPY_WS(S, SLOT)                                                       \
    do {                                                                       \
        const uint32_t _d = slabbase + (SLOT) * STG;                           \
        const float* _gx = xwarp + (size_t)(S) * 64;                           \
        _Pragma("unroll")                                                      \
        for (int p = 0; p < 4; p++) {                                          \
            asm volatile("cp.async.cg.shared.global [%0], [%1], 16;"           \
                :: "r"(_d + xdst + p * 512),                                   \
                   "l"(_gx + (size_t)p * 8 * DIM));                            \
        }                                                                      \
        const char* _gb = reinterpret_cast<const char*>(g_wfrag)               \
                          + ((size_t)(S) * 4 + ks) * 2048 + lane * 16;         \
        _Pragma("unroll")                                                      \
        for (int p = 0; p < 4; p++) {                                          \
            asm volatile("cp.async.cg.shared.global [%0], [%1], 16;"           \
                :: "r"(_d + 2048 + lane * 16 + p * 512), "l"(_gb + p * 512));  \
        }                                                                      \
        asm volatile("cp.async.commit_group;");                                \
    } while (0)

    // ---- consumer loop-invariant offsets (within own slab) ----
    const int t  = lane & 3;
    const int rq = lane >> 2;
    const uint32_t aoff = (uint32_t)(rq * 64 + (((t ^ rq) & 3) << 4));
    const uint32_t boff = 2048u + (uint32_t)lane * 8;

    float acc[2][4][4], acc2[2][4][4];
    #pragma unroll
    for (int mg = 0; mg < 2; mg++)
        #pragma unroll
        for (int nt = 0; nt < 4; nt++)
            #pragma unroll
            for (int q = 0; q < 4; q++) { acc[mg][nt][q] = 0.f; acc2[mg][nt][q] = 0.f; }

    // prologue: stages 0,1 in flight (per warp)
    COPY_WS(0, 0);
    COPY_WS(1, 1);

    int cur = 0, nxt = 2;
    #pragma unroll 1
    for (int s = 0; s < 64; ++s) {
        asm volatile("cp.async.wait_group 1;" ::: "memory");

        // refill stage s+2 into slot (s+2)%3 (this warp read it at stage s-1)
        if (s + 2 < 64) COPY_WS(s + 2, nxt);
        else asm volatile("cp.async.commit_group;");

        const char* slab = smem + cur * STG + wid * WSLAB;

        // B fragments (conflict-free LDS.64, own slab)
        const uint2 q0 = *reinterpret_cast<const uint2*>(slab + boff);
        const uint2 q1 = *reinterpret_cast<const uint2*>(slab + boff + 256);
        const uint2 q2 = *reinterpret_cast<const uint2*>(slab + boff + 512);
        const uint2 q3 = *reinterpret_cast<const uint2*>(slab + boff + 768);
        const uint2 q4 = *reinterpret_cast<const uint2*>(slab + boff + 1024);
        const uint2 q5 = *reinterpret_cast<const uint2*>(slab + boff + 1280);
        const uint2 q6 = *reinterpret_cast<const uint2*>(slab + boff + 1536);
        const uint2 q7 = *reinterpret_cast<const uint2*>(slab + boff + 1792);

        // A fragments (conflict-free LDS.128 via chunk swizzle, own slab)
        const float4 v0 = *reinterpret_cast<const float4*>(slab + aoff);
        const float4 v1 = *reinterpret_cast<const float4*>(slab + aoff + 512);
        const float4 v2 = *reinterpret_cast<const float4*>(slab + aoff + 1024);
        const float4 v3 = *reinterpret_cast<const float4*>(slab + aoff + 1536);

        uint32_t a0[4], a1[4];
        a0[0] = pack_f16x2(v0.x, v0.y);
        a0[1] = pack_f16x2(v1.x, v1.y);
        a0[2] = pack_f16x2(v0.z, v0.w);
        a0[3] = pack_f16x2(v1.z, v1.w);
        a1[0] = pack_f16x2(v2.x, v2.y);
        a1[1] = pack_f16x2(v3.x, v3.y);
        a1[2] = pack_f16x2(v2.z, v2.w);
        a1[3] = pack_f16x2(v3.z, v3.w);

        // 16 independent mmas
        mma16816(acc[0][0], a0, q0.x, q0.y);
        mma16816(acc[0][1], a0, q1.x, q1.y);
        mma16816(acc[0][2], a0, q2.x, q2.y);
        mma16816(acc[0][3], a0, q3.x, q3.y);
        mma16816(acc[1][0], a1, q0.x, q0.y);
        mma16816(acc[1][1], a1, q1.x, q1.y);
        mma16816(acc[1][2], a1, q2.x, q2.y);
        mma16816(acc[1][3], a1, q3.x, q3.y);
        mma16816(acc2[0][0], a0, q4.x, q4.y);
        mma16816(acc2[0][1], a0, q5.x, q5.y);
        mma16816(acc2[0][2], a0, q6.x, q6.y);
        mma16816(acc2[0][3], a0, q7.x, q7.y);
        mma16816(acc2[1][0], a1, q4.x, q4.y);
        mma16816(acc2[1][1], a1, q5.x, q5.y);
        mma16816(acc2[1][2], a1, q6.x, q6.y);
        mma16816(acc2[1][3], a1, q7.x, q7.y);

        cur = (cur == 2) ? 0 : cur + 1;
        nxt = (nxt == 2) ? 0 : nxt + 1;
    }

    asm volatile("cp.async.wait_group 0;" ::: "memory");
    __syncthreads();    // all warps done before aliasing stage buffers
    if (tid == 0) *s_nfl = 0;

    // ---- k-slice tree reduction ----
    const int rslot = mh * 2 + (ks >> 1);
    float* rp = red + rslot * 2048;

    if (ks & 1) {
        #pragma unroll
        for (int mg = 0; mg < 2; mg++)
            #pragma unroll
            for (int nt = 0; nt < 4; nt++)
                #pragma unroll
                for (int q = 0; q < 4; q++) {
                    rp[(mg * 32 + nt * 4 + q) * 32 + lane] = acc[mg][nt][q];
                    rp[(mg * 32 + (nt + 4) * 4 + q) * 32 + lane] = acc2[mg][nt][q];
                }
    }
    __syncthreads();
    if (!(ks & 1)) {
        #pragma unroll
        for (int mg = 0; mg < 2; mg++)
            #pragma unroll
            for (int nt = 0; nt < 4; nt++)
                #pragma unroll
                for (int q = 0; q < 4; q++) {
                    acc[mg][nt][q]  += rp[(mg * 32 + nt * 4 + q) * 32 + lane];
                    acc2[mg][nt][q] += rp[(mg * 32 + (nt + 4) * 4 + q) * 32 + lane];
                }
    }
    __syncthreads();
    if (ks == 2) {
        float* rp2 = red + (mh * 2) * 2048;
        #pragma unroll
        for (int mg = 0; mg < 2; mg++)
            #pragma unroll
            for (int nt = 0; nt < 4; nt++)
                #pragma unroll
                for (int q = 0; q < 4; q++) {
                    rp2[(mg * 32 + nt * 4 + q) * 32 + lane] = acc[mg][nt][q];
                    rp2[(mg * 32 + (nt + 4) * 4 + q) * 32 + lane] = acc2[mg][nt][q];
                }
    }
    __syncthreads();
    if (ks == 0) {
        const float* rp2 = red + (mh * 2) * 2048;
        const int gr = lane >> 2;
        const int gc = (lane & 3) * 2;
        #pragma unroll
        for (int mg = 0; mg < 2; mg++) {
            const int rr0 = mh * 32 + mg * 16 + gr;
            #pragma unroll
            for (int nt = 0; nt < 8; nt++) {
                float* a = (nt < 4) ? acc[mg][nt] : acc2[mg][nt - 4];
                float c0 = a[0] + rp2[(mg * 32 + nt * 4 + 0) * 32 + lane];
                float c1 = a[1] + rp2[(mg * 32 + nt * 4 + 1) * 32 + lane];
                float c2 = a[2] + rp2[(mg * 32 + nt * 4 + 2) * 32 + lane];
                float c3 = a[3] + rp2[(mg * 32 + nt * 4 + 3) * 32 + lane];
                const int cc = nt * 8 + gc;
                slog[rr0 * 65 + cc]           = c0;
                slog[rr0 * 65 + cc + 1]       = c1;
                slog[(rr0 + 8) * 65 + cc]     = c2;
                slog[(rr0 + 8) * 65 + cc + 1] = c3;
            }
        }
    }
    __syncthreads();

    // ---- per-token scan: top-4, logsumexp, flag near-ties ----
    if (tid < BM) {
        const float* r = slog + tid * 65;
        float m1 = -3.4e38f, m2 = -3.4e38f, m3 = -3.4e38f, m4 = -3.4e38f;
        int i1 = 0, i2 = 0, i3 = 0, i4 = 0;
        #pragma unroll
        for (int e = 0; e < NE; e++) {
            float v = r[e];
            if (v > m1)      { m4=m3;i4=i3; m3=m2;i3=i2; m2=m1;i2=i1; m1=v;i1=e; }
            else if (v > m2) { m4=m3;i4=i3; m3=m2;i3=i2; m2=v;i2=e; }
            else if (v > m3) { m4=m3;i4=i3; m3=v;i3=e; }
            else if (v > m4) { m4=v;i4=e; }
        }
        float sum = 0.f;
        #pragma unroll
        for (int e = 0; e < NE; e++) sum += expf(r[e] - m1);
        float lz = m1 + logf(sum);
        out_loss[m_base + tid] = lz * lz;

        float dd = expf(m2 - m1);
        float s1 = 1.f / (1.f + dd);
        s_s1[tid] = s1;
        s_s2[tid] = dd * s1;
        s_i1[tid] = i1;
        s_i2[tid] = i2;

        int ent = -1;
        if (m2 - m3 < TAU) {
            int fs = atomicAdd(s_nfl, 1);
            if (fs < MAXF) {
                ent = fs;
                f_tok[ent] = tid;
                f_cand[ent * 4 + 0] = i1;
                f_cand[ent * 4 + 1] = i2;
                f_cand[ent * 4 + 2] = i3;
                f_cand[ent * 4 + 3] = i4;
            }
        }
        s_fent[tid] = ent;
    }
    __syncthreads();

    // ---- exact fp32 refinement: one warp per (flagged token, candidate) ----
    {
        int nf = *s_nfl; if (nf > MAXF) nf = MAXF;
        for (int task = wid; task < nf * 4; task += 8) {
            const int fi = task >> 2, c = task & 3;
            const int tok = f_tok[fi];
            const int expert = f_cand[fi * 4 + c];
            const float* xr = x + (m_base + tok) * DIM;
            const float* wr = Wf + (size_t)expert * DIM;
            float a4[4] = {0.f, 0.f, 0.f, 0.f};
            for (int k = lane * 4; k < DIM; k += 128) {
                float4 xv = *reinterpret_cast<const float4*>(xr + k);
                float4 wv = *reinterpret_cast<const float4*>(wr + k);
                a4[0] = fmaf(xv.x, wv.x, a4[0]);
                a4[1] = fmaf(xv.y, wv.y, a4[1]);
                a4[2] = fmaf(xv.z, wv.z, a4[2]);
                a4[3] = fmaf(xv.w, wv.w, a4[3]);
            }
            float sum = (a4[0] + a4[1]) + (a4[2] + a4[3]);
            #pragma unroll
            for (int off = 16; off; off >>= 1)
                sum += __shfl_xor_sync(0xffffffffu, sum, off);
            if (lane == 0) f_val[fi * 4 + c] = sum;
        }
    }
    __syncthreads();

    // ---- flagged tokens: re-pick exact top-2 (stable ties by lower index) ----
    if (tid < BM && s_fent[tid] >= 0) {
        const int ent = s_fent[tid];
        float v1 = -3.4e38f, v2 = -3.4e38f;
        int j1 = NE, j2 = NE;
        #pragma unroll
        for (int c = 0; c < 4; c++) {
            float v = f_val[ent * 4 + c];
            int   j = f_cand[ent * 4 + c];
            bool b1 = (v > v1) || (v == v1 && j < j1);
            bool b2 = (v > v2) || (v == v2 && j < j2);
            if (b1)      { v2 = v1; j2 = j1; v1 = v; j1 = j; }
            else if (b2) { v2 = v; j2 = j; }
        }
        float dd = expf(v2 - v1);
        float s1 = 1.f / (1.f + dd);
        s_s1[tid] = s1;
        s_s2[tid] = dd * s1;
        s_i1[tid] = j1;
        s_i2[tid] = j2;
    }
    __syncthreads();

    // ---- stores ----
    float* lg = out_logits + m_base * NE;
    float* sc = out_scores + m_base * NE;
    #pragma unroll
    for (int pass = 0; pass < (BM * NE) / NTHR; pass++) {
        int idx = pass * NTHR + tid;
        int tt = idx >> 6;
        int e = idx & 63;
        lg[idx] = slog[tt * 65 + e];
        float sv = (e == s_i1[tt]) ? s_s1[tt] : ((e == s_i2[tt]) ? s_s2[tt] : 0.f);
        sc[idx] = sv;
    }
#undef COPY_WS
}

extern "C" void kernel_launch(void* const* d_in, const int* in_sizes, int n_in,
                              void* d_out, int out_size)
{
    const float* x = (const float*)d_in[0];
    const float* W = (const float*)d_in[1];
    float* out    = (float*)d_out;
    float* logits = out;
    float* scores = out + (size_t)TOKENS * NE;
    float* loss   = out + (size_t)2 * TOKENS * NE;

    prep_w<<<256, 256>>>(W);

    cudaFuncSetAttribute(topk_gate_wp,
                         cudaFuncAttributeMaxDynamicSharedMemorySize, SMEM_TOTAL);
    topk_gate_wp<<<TOKENS / BM, NTHR, SMEM_TOTAL>>>(x, W, logits, scores, loss);
}